// round 1
// baseline (speedup 1.0000x reference)
#include <cuda_runtime.h>
#include <cuda_bf16.h>

// Problem constants (fixed by the reference)
#define Bq   4
#define Lq   100
#define Mq   2048
#define Eq   50
#define EX_SU_INV (1.0f / 1000.0f)
#define EX_TU_INV (1.0f / 86400.0f)

#define TM      512      // m-values per block
#define THREADS 256
#define NCHUNK  (Mq / TM)        // 4
#define NV      (TM * Eq / 4)    // 6400 float4 per block

__global__ __launch_bounds__(THREADS)
void ctr_embedding_kernel(const int*   __restrict__ traj_location,  // [B,L]
                          const float* __restrict__ mat2,           // [NLOC,M]
                          const float* __restrict__ vector,         // [B,L]
                          const int*   __restrict__ traj_length,    // [B]
                          const float* __restrict__ emb_su,         // [2,E]
                          const float* __restrict__ emb_sl,
                          const float* __restrict__ emb_tu,
                          const float* __restrict__ emb_tl,
                          float*       __restrict__ out)            // [B,L,M,E]
{
    __shared__ float  s_ds[TM];
    __shared__ float2 s_bs[Eq];   // (base[e], slope[e])

    const int bl    = blockIdx.x;          // 0 .. B*L-1
    const int chunk = blockIdx.y;          // 0 .. NCHUNK-1
    const int b     = bl / Lq;
    const int l     = bl - b * Lq;
    const int m0    = chunk * TM;
    const int tid   = threadIdx.x;

    const bool valid = (l < traj_length[b]);

    // Stage gathered mat2 slice (or zeros) into smem, coalesced.
    if (valid) {
        const int loc = traj_location[bl] - 1;          // 1-based -> 0-based
        const float* row = mat2 + (size_t)loc * Mq + m0;
        #pragma unroll
        for (int i = tid; i < TM; i += THREADS) s_ds[i] = row[i];
    } else {
        #pragma unroll
        for (int i = tid; i < TM; i += THREADS) s_ds[i] = 0.0f;
    }

    // Precompute per-(b,l) base/slope vectors over E.
    if (tid < Eq) {
        const int off = (valid ? 1 : 0) * Eq + tid;
        const float dt = vector[bl];
        const float tl = emb_tl[off], tu = emb_tu[off];
        const float sl = emb_sl[off], su = emb_su[off];
        // time_interval = tl + (tu - tl) * dt / EX_TU   (EX_TL = 0)
        const float time_i = fmaf(tu - tl, dt * EX_TU_INV, tl);
        // space_interval = sl + (su - sl) * ds / EX_SU  (EX_SL = 0)
        s_bs[tid] = make_float2(sl + time_i, (su - sl) * EX_SU_INV);
    }
    __syncthreads();

    // Flat streaming over TM*E elements, 4 at a time (16B-aligned: TM*E % 4 == 0,
    // block base ((bl*M + m0)*E) % 4 == 0).
    float4* __restrict__ outv =
        (float4*)(out + ((size_t)bl * Mq + (size_t)m0) * Eq);

    for (int v = tid; v < NV; v += THREADS) {
        const int f = v * 4;
        int m = f / Eq;
        int e = f - m * Eq;
        float  d = s_ds[m];
        float2 c;
        float4 r;

        c = s_bs[e]; r.x = fmaf(c.y, d, c.x);
        if (++e == Eq) { e = 0; d = s_ds[++m]; }
        c = s_bs[e]; r.y = fmaf(c.y, d, c.x);
        if (++e == Eq) { e = 0; d = s_ds[++m]; }
        c = s_bs[e]; r.z = fmaf(c.y, d, c.x);
        if (++e == Eq) { e = 0; d = s_ds[++m]; }
        c = s_bs[e]; r.w = fmaf(c.y, d, c.x);

        outv[v] = r;
    }
}

extern "C" void kernel_launch(void* const* d_in, const int* in_sizes, int n_in,
                              void* d_out, int out_size)
{
    const int*   traj_location = (const int*)  d_in[0];
    const float* mat2          = (const float*)d_in[1];
    const float* vector        = (const float*)d_in[2];
    const int*   traj_length   = (const int*)  d_in[3];
    const float* emb_su        = (const float*)d_in[4];
    const float* emb_sl        = (const float*)d_in[5];
    const float* emb_tu        = (const float*)d_in[6];
    const float* emb_tl        = (const float*)d_in[7];
    float* out = (float*)d_out;

    dim3 grid(Bq * Lq, NCHUNK);
    ctr_embedding_kernel<<<grid, THREADS>>>(traj_location, mat2, vector,
                                            traj_length, emb_su, emb_sl,
                                            emb_tu, emb_tl, out);
}

// round 2
// speedup vs baseline: 1.1842x; 1.1842x over previous
#include <cuda_runtime.h>
#include <cuda_bf16.h>

// Problem constants (fixed by the reference)
#define Bq   4
#define Lq   100
#define Mq   2048
#define Eq   50
#define EX_SU_INV (1.0f / 1000.0f)
#define EX_TU_INV (1.0f / 86400.0f)

#define TM      512              // m-values per block
#define THREADS 256              // 8 warps
#define NCHUNK  (Mq / TM)        // 4
#define NPAIR   (TM / 2)         // 256 m-pairs per block (one pair = 100 floats = 25 float4)
#define NWARP   (THREADS / 32)

__global__ __launch_bounds__(THREADS)
void ctr_embedding_kernel(const int*   __restrict__ traj_location,  // [B,L]
                          const float* __restrict__ mat2,           // [NLOC,M]
                          const float* __restrict__ vector,         // [B,L]
                          const int*   __restrict__ traj_length,    // [B]
                          const float* __restrict__ emb_su,         // [2,E]
                          const float* __restrict__ emb_sl,
                          const float* __restrict__ emb_tu,
                          const float* __restrict__ emb_tl,
                          float*       __restrict__ out)            // [B,L,M,E]
{
    __shared__ float  s_ds[TM];   // gathered mat2 slice (or zeros)
    __shared__ float2 s_bs[Eq];   // (base[e], slope[e])

    const int bl    = blockIdx.x;          // 0 .. B*L-1
    const int chunk = blockIdx.y;          // 0 .. NCHUNK-1
    const int b     = bl / Lq;
    const int l     = bl - b * Lq;
    const int m0    = chunk * TM;
    const int tid   = threadIdx.x;

    const bool valid = (l < traj_length[b]);

    // Stage gathered mat2 slice (or zeros) into smem, coalesced.
    if (valid) {
        const int loc = traj_location[bl] - 1;          // 1-based -> 0-based
        const float* row = mat2 + (size_t)loc * Mq + m0;
        #pragma unroll
        for (int i = tid; i < TM; i += THREADS) s_ds[i] = row[i];
    } else {
        #pragma unroll
        for (int i = tid; i < TM; i += THREADS) s_ds[i] = 0.0f;
    }

    // Precompute per-(b,l) base/slope vectors over E.
    if (tid < Eq) {
        const int off = (valid ? 1 : 0) * Eq + tid;
        const float dt = vector[bl];
        const float tl = emb_tl[off], tu = emb_tu[off];
        const float sl = emb_sl[off], su = emb_su[off];
        // time_interval = tl + (tu - tl) * dt / EX_TU   (EX_TL = 0)
        const float time_i = fmaf(tu - tl, dt * EX_TU_INV, tl);
        // space_interval = sl + (su - sl) * ds / EX_SU  (EX_SL = 0)
        s_bs[tid] = make_float2(sl + time_i, (su - sl) * EX_SU_INV);
    }
    __syncthreads();

    // One warp per m-pair iteration. A pair = 100 floats = 25 float4s; lane
    // ell (< 25) always owns floats [4*ell, 4*ell+3] of the pair, so its four
    // (base, slope) constants are loop-invariant -> registers. Inner loop is
    // just: 1 broadcast LDS.64 of (d[m0], d[m1]), 4 SEL, 4 FFMA, 1 STG.128.
    const int wid  = tid >> 5;
    const int lane = tid & 31;

    if (lane < 25) {
        const int f = 4 * lane;                // float offset within 100-float pair
        // Registerize constants for the 4 elements this lane owns.
        const int  e0 = f % Eq,            e1 = (f + 1) % Eq;
        const int  e2 = (f + 2) % Eq,      e3 = (f + 3) % Eq;
        const bool u0 = (f     >= Eq),     u1 = (f + 1 >= Eq);
        const bool u2 = (f + 2 >= Eq),     u3 = (f + 3 >= Eq);
        const float2 c0 = s_bs[e0], c1 = s_bs[e1];
        const float2 c2 = s_bs[e2], c3 = s_bs[e3];

        const float2* __restrict__ ds2 = (const float2*)s_ds;
        float4* __restrict__ outv =
            (float4*)(out + ((size_t)bl * Mq + (size_t)m0) * Eq) + lane;

        #pragma unroll 4
        for (int pair = wid; pair < NPAIR; pair += NWARP) {
            const float2 dd = ds2[pair];       // (d[m_even], d[m_odd]) broadcast
            float4 r;
            r.x = fmaf(c0.y, u0 ? dd.y : dd.x, c0.x);
            r.y = fmaf(c1.y, u1 ? dd.y : dd.x, c1.x);
            r.z = fmaf(c2.y, u2 ? dd.y : dd.x, c2.x);
            r.w = fmaf(c3.y, u3 ? dd.y : dd.x, c3.x);
            __stcs(outv + pair * 25, r);       // evict-first: output >> L2
        }
    }
}

extern "C" void kernel_launch(void* const* d_in, const int* in_sizes, int n_in,
                              void* d_out, int out_size)
{
    const int*   traj_location = (const int*)  d_in[0];
    const float* mat2          = (const float*)d_in[1];
    const float* vector        = (const float*)d_in[2];
    const int*   traj_length   = (const int*)  d_in[3];
    const float* emb_su        = (const float*)d_in[4];
    const float* emb_sl        = (const float*)d_in[5];
    const float* emb_tu        = (const float*)d_in[6];
    const float* emb_tl        = (const float*)d_in[7];
    float* out = (float*)d_out;

    dim3 grid(Bq * Lq, NCHUNK);
    ctr_embedding_kernel<<<grid, THREADS>>>(traj_location, mat2, vector,
                                            traj_length, emb_su, emb_sl,
                                            emb_tu, emb_tl, out);
}

// round 3
// speedup vs baseline: 1.2126x; 1.0240x over previous
#include <cuda_runtime.h>
#include <cuda_bf16.h>

// Problem constants (fixed by the reference)
#define Bq   4
#define Lq   100
#define Mq   2048
#define Eq   50
#define EX_SU_INV (1.0f / 1000.0f)
#define EX_TU_INV (1.0f / 86400.0f)

#define TM      512              // m-values per block
#define THREADS 256              // 8 warps
#define NCHUNK  (Mq / TM)        // 4
#define NGROUP  (TM / 4)         // 128 groups of 4 m (one group = 200 floats = 25 float8)
#define NWARP   (THREADS / 32)

__global__ __launch_bounds__(THREADS)
void ctr_embedding_kernel(const int*   __restrict__ traj_location,  // [B,L]
                          const float* __restrict__ mat2,           // [NLOC,M]
                          const float* __restrict__ vector,         // [B,L]
                          const int*   __restrict__ traj_length,    // [B]
                          const float* __restrict__ emb_su,         // [2,E]
                          const float* __restrict__ emb_sl,
                          const float* __restrict__ emb_tu,
                          const float* __restrict__ emb_tl,
                          float*       __restrict__ out)            // [B,L,M,E]
{
    __shared__ float  s_ds[TM];   // gathered mat2 slice (or zeros)
    __shared__ float2 s_bs[Eq];   // (base[e], slope[e])

    const int bl    = blockIdx.x;          // 0 .. B*L-1
    const int chunk = blockIdx.y;          // 0 .. NCHUNK-1
    const int b     = bl / Lq;
    const int l     = bl - b * Lq;
    const int m0    = chunk * TM;
    const int tid   = threadIdx.x;

    const bool valid = (l < traj_length[b]);

    // Stage gathered mat2 slice (or zeros) into smem, coalesced.
    if (valid) {
        const int loc = traj_location[bl] - 1;          // 1-based -> 0-based
        const float* row = mat2 + (size_t)loc * Mq + m0;
        #pragma unroll
        for (int i = tid; i < TM; i += THREADS) s_ds[i] = row[i];
    } else {
        #pragma unroll
        for (int i = tid; i < TM; i += THREADS) s_ds[i] = 0.0f;
    }

    // Precompute per-(b,l) base/slope vectors over E.
    if (tid < Eq) {
        const int off = (valid ? 1 : 0) * Eq + tid;
        const float dt = vector[bl];
        const float tl = emb_tl[off], tu = emb_tu[off];
        const float sl = emb_sl[off], su = emb_su[off];
        // time_interval = tl + (tu - tl) * dt / EX_TU   (EX_TL = 0)
        const float time_i = fmaf(tu - tl, dt * EX_TU_INV, tl);
        // space_interval = sl + (su - sl) * ds / EX_SU  (EX_SL = 0)
        s_bs[tid] = make_float2(sl + time_i, (su - sl) * EX_SU_INV);
    }
    __syncthreads();

    // One warp per 4-m group (200 floats = 25 float8). Lane ell (< 25) owns
    // floats [8*ell, 8*ell+7] of every group, so its 8 (base, slope) pairs are
    // loop-invariant registers. 8 < 50 => a lane crosses at most ONE m
    // boundary within the group: two candidate d values (d_lo, d_hi) picked
    // from one broadcast LDS.128. Inner loop: 1 LDS.128 + ~12 SEL + 8 FFMA +
    // 1 STG.256 (800 B per LSU store instruction).
    const int wid  = tid >> 5;
    const int lane = tid & 31;

    if (lane < 25) {
        const int f = 8 * lane;               // float offset within 200-float group
        // Loop-invariant per-lane constants.
        float2 c[8];
        bool   hi[8];
        const int u_lo = f / Eq;                       // m index (in group) of float f
        const int s    = Eq * (u_lo + 1) - f;          // switch position (>=8 => no switch)
        const int u_hi = u_lo + (s < 8 ? 1 : 0);
        #pragma unroll
        for (int j = 0; j < 8; j++) {
            c[j]  = s_bs[(f + j) % Eq];
            hi[j] = (j >= s);
        }

        const float4* __restrict__ ds4 = (const float4*)s_ds;
        float* __restrict__ outp =
            out + ((size_t)bl * Mq + (size_t)m0) * Eq + f;

        #pragma unroll 4
        for (int g = wid; g < NGROUP; g += NWARP) {
            const float4 dd = ds4[g];          // d for the 4 m's, broadcast
            const float d_lo = (u_lo == 0) ? dd.x : (u_lo == 1) ? dd.y
                             : (u_lo == 2) ? dd.z : dd.w;
            const float d_hi = (u_hi == 0) ? dd.x : (u_hi == 1) ? dd.y
                             : (u_hi == 2) ? dd.z : dd.w;
            float r[8];
            #pragma unroll
            for (int j = 0; j < 8; j++)
                r[j] = fmaf(c[j].y, hi[j] ? d_hi : d_lo, c[j].x);

            // 256-bit store, evict-first (output stream >> L2).
            asm volatile(
                "st.global.cs.v8.f32 [%0], {%1,%2,%3,%4,%5,%6,%7,%8};"
                :: "l"(outp + (size_t)g * 200),
                   "f"(r[0]), "f"(r[1]), "f"(r[2]), "f"(r[3]),
                   "f"(r[4]), "f"(r[5]), "f"(r[6]), "f"(r[7])
                : "memory");
        }
    }
}

extern "C" void kernel_launch(void* const* d_in, const int* in_sizes, int n_in,
                              void* d_out, int out_size)
{
    const int*   traj_location = (const int*)  d_in[0];
    const float* mat2          = (const float*)d_in[1];
    const float* vector        = (const float*)d_in[2];
    const int*   traj_length   = (const int*)  d_in[3];
    const float* emb_su        = (const float*)d_in[4];
    const float* emb_sl        = (const float*)d_in[5];
    const float* emb_tu        = (const float*)d_in[6];
    const float* emb_tl        = (const float*)d_in[7];
    float* out = (float*)d_out;

    dim3 grid(Bq * Lq, NCHUNK);
    ctr_embedding_kernel<<<grid, THREADS>>>(traj_location, mat2, vector,
                                            traj_length, emb_su, emb_sl,
                                            emb_tu, emb_tl, out);
}

// round 4
// speedup vs baseline: 1.2898x; 1.0637x over previous
#include <cuda_runtime.h>
#include <cuda_bf16.h>

// Problem constants (fixed by the reference)
#define Bq   4
#define Lq   100
#define Mq   2048
#define Eq   50
#define EX_SU_INV (1.0f / 1000.0f)
#define EX_TU_INV (1.0f / 86400.0f)

#define TM      512              // m-values per block
#define NCHUNK  (Mq / TM)        // 4
#define THREADS 416              // 13 warps; threads 0..399 active in mainloop
#define ACTIVE  400
#define WINM    32               // m per window
#define WINF    (WINM * Eq)      // 1600 floats per window = ACTIVE * 4
#define NITER   (TM / WINM)      // 16 windows per block

__global__ __launch_bounds__(THREADS)
void ctr_embedding_kernel(const int*   __restrict__ traj_location,  // [B,L]
                          const float* __restrict__ mat2,           // [NLOC,M]
                          const float* __restrict__ vector,         // [B,L]
                          const int*   __restrict__ traj_length,    // [B]
                          const float* __restrict__ emb_su,         // [2,E]
                          const float* __restrict__ emb_sl,
                          const float* __restrict__ emb_tu,
                          const float* __restrict__ emb_tl,
                          float*       __restrict__ out)            // [B,L,M,E]
{
    __shared__ float  s_ds[TM];   // gathered mat2 slice (or zeros)
    __shared__ float2 s_bs[Eq];   // (base[e], slope[e])

    const int bl    = blockIdx.x;          // 0 .. B*L-1
    const int chunk = blockIdx.y;          // 0 .. NCHUNK-1
    const int b     = bl / Lq;
    const int l     = bl - b * Lq;
    const int m0    = chunk * TM;
    const int tid   = threadIdx.x;

    const bool valid = (l < traj_length[b]);

    // Stage gathered mat2 slice (or zeros) into smem, coalesced.
    if (valid) {
        const int loc = traj_location[bl] - 1;          // 1-based -> 0-based
        const float* row = mat2 + (size_t)loc * Mq + m0;
        for (int i = tid; i < TM; i += THREADS) s_ds[i] = row[i];
    } else {
        for (int i = tid; i < TM; i += THREADS) s_ds[i] = 0.0f;
    }

    // Precompute per-(b,l) base/slope vectors over E.
    if (tid < Eq) {
        const int off = (valid ? 1 : 0) * Eq + tid;
        const float dt = vector[bl];
        const float tl = emb_tl[off], tu = emb_tu[off];
        const float sl = emb_sl[off], su = emb_su[off];
        // time_interval = tl + (tu - tl) * dt / EX_TU   (EX_TL = 0)
        const float time_i = fmaf(tu - tl, dt * EX_TU_INV, tl);
        // space_interval = sl + (su - sl) * ds / EX_SU  (EX_SL = 0)
        s_bs[tid] = make_float2(sl + time_i, (su - sl) * EX_SU_INV);
    }
    __syncthreads();

    // Window scheme: 1600 floats (= 32 m = 400 float4) per window. Thread
    // t < 400 always owns floats [4t, 4t+3] of every window, so its e-phase
    // (4t mod 50) is loop-invariant -> constants live in registers. A float4
    // crosses at most one m boundary; split-slope (sl_lo / sl_hi with zeros)
    // removes all SELs: r = fma(sl_hi, d_hi, fma(sl_lo, d_lo, base)).
    // Inner loop: 2 broadcast LDS.32 + 8 FFMA + 1 STG.128.
    if (tid < ACTIVE) {
        const int f    = 4 * tid;              // float offset in window
        const int m_lo = f / Eq;               // m (within window) of float f
        const int m_hi = (f + 3) / Eq;         // m of float f+3
        const int s    = Eq * (m_lo + 1) - f;  // first j using d_hi (>=4 => none)

        float base[4], sl_lo[4], sl_hi[4];
        #pragma unroll
        for (int j = 0; j < 4; j++) {
            const float2 c = s_bs[(f + j) % Eq];
            base[j]  = c.x;
            sl_lo[j] = (j < s) ? c.y : 0.0f;
            sl_hi[j] = c.y - sl_lo[j];
        }

        float* __restrict__ outp =
            out + ((size_t)bl * Mq + (size_t)m0) * Eq + f;

        #pragma unroll 4
        for (int w = 0; w < NITER; w++) {
            const int mb = w * WINM;
            const float d_lo = s_ds[mb + m_lo];
            const float d_hi = s_ds[mb + m_hi];
            float r[4];
            #pragma unroll
            for (int j = 0; j < 4; j++)
                r[j] = fmaf(sl_hi[j], d_hi, fmaf(sl_lo[j], d_lo, base[j]));

            // 128-bit store, evict-first (output stream >> L2).
            asm volatile(
                "st.global.cs.v4.f32 [%0], {%1,%2,%3,%4};"
                :: "l"(outp + (size_t)w * WINF),
                   "f"(r[0]), "f"(r[1]), "f"(r[2]), "f"(r[3])
                : "memory");
        }
    }
}

extern "C" void kernel_launch(void* const* d_in, const int* in_sizes, int n_in,
                              void* d_out, int out_size)
{
    const int*   traj_location = (const int*)  d_in[0];
    const float* mat2          = (const float*)d_in[1];
    const float* vector        = (const float*)d_in[2];
    const int*   traj_length   = (const int*)  d_in[3];
    const float* emb_su        = (const float*)d_in[4];
    const float* emb_sl        = (const float*)d_in[5];
    const float* emb_tu        = (const float*)d_in[6];
    const float* emb_tl        = (const float*)d_in[7];
    float* out = (float*)d_out;

    dim3 grid(Bq * Lq, NCHUNK);
    ctr_embedding_kernel<<<grid, THREADS>>>(traj_location, mat2, vector,
                                            traj_length, emb_su, emb_sl,
                                            emb_tu, emb_tl, out);
}